// round 4
// baseline (speedup 1.0000x reference)
#include <cuda_runtime.h>
#include <cuda_bf16.h>
#include <math.h>
#include <float.h>
#include <stdint.h>

// ---------------------------------------------------------------------------
// DeepRare: per-channel rarity collapses to a 6-entry LUT per channel.
// Launches: init -> (mm_i -> hist_i) x5 (L2-resident 2nd pass) -> stats ->
// proc(all, fused pminmax for l1-3) -> mm45 -> resize(all) -> final.
// ---------------------------------------------------------------------------

#define NCH 1472
#define GIDX_TOTAL 28108800

__device__ unsigned g_cmin[NCH], g_cmax[NCH];
__device__ unsigned g_hist[NCH][6], g_hist2[NCH][6];
__device__ float g_M[NCH][6], g_Z[NCH];
__device__ __align__(16) unsigned char g_gidx[GIDX_TOTAL];
__device__ __align__(16) float g_proc[306912];
__device__ unsigned g_pmin[5], g_pmax[5];
__device__ float g_resized[5 * 57600];
__device__ unsigned g_rmin[5], g_rmax[5];
__device__ float g_rsum[5];

// order-preserving float<->uint encoding for atomic min/max
__device__ __forceinline__ unsigned fenc(float f) {
    unsigned u = __float_as_uint(f);
    return (u & 0x80000000u) ? ~u : (u | 0x80000000u);
}
__device__ __forceinline__ float fdec(unsigned e) {
    return (e & 0x80000000u) ? __uint_as_float(e & 0x7fffffffu)
                             : __uint_as_float(~e);
}

__global__ void k_init() {
    int i = blockIdx.x * 256 + threadIdx.x;
    if (i < NCH * 6) {
        ((unsigned*)g_hist)[i] = 0u;
        ((unsigned*)g_hist2)[i] = 0u;
    }
    if (i < NCH) { g_cmin[i] = 0xffffffffu; g_cmax[i] = 0u; }
    if (i < 4500) g_proc[302400 + i] = 0.f;   // l4+l5 (atomic-accumulated)
    if (i < 5) {
        g_pmin[i] = 0xffffffffu; g_pmax[i] = 0u;
        g_rmin[i] = 0xffffffffu; g_rmax[i] = 0u;
        g_rsum[i] = 0.f;
    }
}

// ---- shared: masked float4 load (borders -> 0), constexpr unrolled --------
template <int H, int W>
__device__ __forceinline__ void mask4(int fc, float4 v,
                                      float& v0, float& v1, float& v2, float& v3) {
    if constexpr (W % 4 == 0) {
        constexpr int W4 = W / 4;
        int row = fc / W4;
        int col = fc - row * W4;
        bool br = (row == 0) | (row == H - 1);
        v0 = (br | (col == 0))      ? 0.f : v.x;
        v1 = br                      ? 0.f : v.y;
        v2 = br                      ? 0.f : v.z;
        v3 = (br | (col == W4 - 1)) ? 0.f : v.w;
    } else {
        int e = fc * 4;
        int y0 = e / W, x0 = e - y0 * W;
        int y1 = (e+1) / W, x1 = (e+1) - y1 * W;
        int y2 = (e+2) / W, x2 = (e+2) - y2 * W;
        int y3 = (e+3) / W, x3 = (e+3) - y3 * W;
        v0 = ((y0==0)|(x0==0)|(y0==H-1)|(x0==W-1)) ? 0.f : v.x;
        v1 = ((y1==0)|(x1==0)|(y1==H-1)|(x1==W-1)) ? 0.f : v.y;
        v2 = ((y2==0)|(x2==0)|(y2==H-1)|(x2==W-1)) ? 0.f : v.z;
        v3 = ((y3==0)|(x3==0)|(y3==H-1)|(x3==W-1)) ? 0.f : v.w;
    }
}

// -------- K1: per-channel min/max over zero-bordered channel ---------------
template <int H, int W, int SLICES>
__device__ __forceinline__ void mm_layer(const float* __restrict__ in,
                                         int choff, int blk) {
    constexpr int HWf4 = H * W / 4;
    constexpr int SL = HWf4 / SLICES;
    constexpr int F4PT = (SL + 255) / 256;
    const int c = blk / SLICES;
    const int s = blk - c * SLICES;
    const float4* p4 = (const float4*)in + (size_t)c * HWf4 + s * SL;
    const int fbase = s * SL;
    float mn = FLT_MAX, mx = -FLT_MAX;
#pragma unroll
    for (int j = 0; j < F4PT; j++) {
        int fl = j * 256 + threadIdx.x;
        if (SL % 256 == 0 || fl < SL) {
            float4 v = p4[fl];
            float v0, v1, v2, v3;
            mask4<H, W>(fbase + fl, v, v0, v1, v2, v3);
            mn = fminf(mn, fminf(fminf(v0, v1), fminf(v2, v3)));
            mx = fmaxf(mx, fmaxf(fmaxf(v0, v1), fmaxf(v2, v3)));
        }
    }
    unsigned emn = __reduce_min_sync(0xffffffffu, fenc(mn));
    unsigned emx = __reduce_max_sync(0xffffffffu, fenc(mx));
    if ((threadIdx.x & 31) == 0) {
        atomicMin(&g_cmin[choff + c], emn);
        atomicMax(&g_cmax[choff + c], emx);
    }
}

__global__ __launch_bounds__(256) void k_mm1(const float* __restrict__ p) { mm_layer<480, 480, 15>(p, 0, blockIdx.x); }
__global__ __launch_bounds__(256) void k_mm2(const float* __restrict__ p) { mm_layer<240, 240, 4>(p, 64, blockIdx.x); }
__global__ __launch_bounds__(256) void k_mm3(const float* __restrict__ p) { mm_layer<120, 120, 1>(p, 192, blockIdx.x); }
__global__ __launch_bounds__(256) void k_mm4(const float* __restrict__ p) { mm_layer<60, 60, 1>(p, 448, blockIdx.x); }
__global__ __launch_bounds__(256) void k_mm5(const float* __restrict__ p) { mm_layer<30, 30, 1>(p, 960, blockIdx.x); }

// -------- K2: dual 6-bin histogram + gidx map ------------------------------
// gidx path stays bit-exact (div.rn). The 6-bin "bin" only feeds histogram
// counts (insensitive through -log(h/N + 1e-4)), so chp/binw is replaced by
// chp * (1/binw).
template <int H, int W, int SLICES>
__device__ __forceinline__ void hist_layer(const float* __restrict__ in,
                                           int choff, size_t gidxoff, int blk) {
    constexpr int HWf4 = H * W / 4;
    constexpr int SL = HWf4 / SLICES;
    constexpr int F4PT = (SL + 255) / 256;
    const int c = blk / SLICES;
    const int s = blk - c * SLICES;
    const int gc = choff + c;
    const float4* p4 = (const float4*)in + (size_t)c * HWf4 + s * SL;
    uchar4* go = (uchar4*)(g_gidx + gidxoff) + (size_t)c * HWf4 + s * SL;
    const int fbase = s * SL;
    const float mn = fdec(g_cmin[gc]);
    const float mx = fdec(g_cmax[gc]);
    const float rng = mx - mn;
    const bool zr = (rng == 0.f);
    const float ib = 1.0f / (256.0f / 6.0f);   // compile-time folded
    unsigned long long pk1 = 0, pk2 = 0;   // 6 x 10-bit packed counters
#pragma unroll
    for (int j = 0; j < F4PT; j++) {
        int fl = j * 256 + threadIdx.x;
        if (SL % 256 == 0 || fl < SL) {
            float4 v = p4[fl];
            float vv[4];
            mask4<H, W>(fbase + fl, v, vv[0], vv[1], vv[2], vv[3]);
            unsigned gb[4];
#pragma unroll
            for (int k = 0; k < 4; k++) {
                float q = zr ? 0.f : __fdiv_rn(__fsub_rn(vv[k], mn), rng);
                float chp = __fmul_rn(q, 256.f);
                int bin = (int)floorf(__fmul_rn(chp, ib));
                bin = min(5, max(0, bin));
                int g = (int)truncf(__fsub_rn(__fmul_rn(chp, 6.f), 1.f));
                g = min(5, max(0, g));
                pk1 += 1ull << (bin * 10);
                pk2 += 1ull << (g * 10);
                gb[k] = (unsigned)g;
            }
            go[fl] = make_uchar4(gb[0], gb[1], gb[2], gb[3]);
        }
    }
    __shared__ unsigned sh[12];
    if (threadIdx.x < 12) sh[threadIdx.x] = 0;
    __syncthreads();
#pragma unroll
    for (int b6 = 0; b6 < 6; b6++) {
        unsigned c1 = (unsigned)(pk1 >> (b6 * 10)) & 1023u;
        unsigned c2 = (unsigned)(pk2 >> (b6 * 10)) & 1023u;
        c1 = __reduce_add_sync(0xffffffffu, c1);
        c2 = __reduce_add_sync(0xffffffffu, c2);
        if ((threadIdx.x & 31) == 0) {
            if (c1) atomicAdd(&sh[b6], c1);
            if (c2) atomicAdd(&sh[6 + b6], c2);
        }
    }
    __syncthreads();
    if (threadIdx.x < 6 && sh[threadIdx.x])
        atomicAdd(&g_hist[gc][threadIdx.x], sh[threadIdx.x]);
    if (threadIdx.x >= 6 && threadIdx.x < 12 && sh[threadIdx.x])
        atomicAdd(&g_hist2[gc][threadIdx.x - 6], sh[threadIdx.x]);
}

__global__ __launch_bounds__(256) void k_h1(const float* __restrict__ p) { hist_layer<480, 480, 15>(p, 0, 0, blockIdx.x); }
__global__ __launch_bounds__(256) void k_h2(const float* __restrict__ p) { hist_layer<240, 240, 4>(p, 64, 14745600u, blockIdx.x); }
__global__ __launch_bounds__(256) void k_h3(const float* __restrict__ p) { hist_layer<120, 120, 1>(p, 192, 22118400u, blockIdx.x); }
__global__ __launch_bounds__(256) void k_h4(const float* __restrict__ p) { hist_layer<60, 60, 1>(p, 448, 25804800u, blockIdx.x); }
__global__ __launch_bounds__(256) void k_h5(const float* __restrict__ p) { hist_layer<30, 30, 1>(p, 960, 27648000u, blockIdx.x); }

// -------- K3: closed-form per-channel tables (all-float, spread wide) ------
__global__ void k_stats_all() {
    int gc = blockIdx.x * 32 + threadIdx.x;
    if (gc >= NCH) return;
    int choff, H, W;
    if (gc < 64)       { choff = 0;   H = 480; W = 480; }
    else if (gc < 192) { choff = 64;  H = 240; W = 240; }
    else if (gc < 448) { choff = 192; H = 120; W = 120; }
    else if (gc < 960) { choff = 448; H = 60;  W = 60;  }
    else               { choff = 960; H = 30;  W = 30;  }
    const int c = gc - choff;
    const float Nf = (float)(H * W);
    const int Nb = 2 * (H + W) - 4;

    float mn = fdec(g_cmin[gc]), mx = fdec(g_cmax[gc]);
    float rng = mx - mn;

    float hl[6]; unsigned h2[6];
#pragma unroll
    for (int b = 0; b < 6; b++) {
        float pr = __fadd_rn(__fdiv_rn((float)g_hist[gc][b], Nf), 1e-4f);
        hl[b] = -logf(pr);
        h2[b] = g_hist2[gc][b];
    }
    float dmin = FLT_MAX, dmax = -FLT_MAX, s = 0.f;
#pragma unroll
    for (int b = 0; b < 6; b++) if (h2[b]) {
        dmin = fminf(dmin, hl[b]); dmax = fmaxf(dmax, hl[b]);
        s += (float)h2[b] * hl[b];
    }
    float drng = dmax - dmin;
    float L[6];
    if (drng == 0.f) {
#pragma unroll
        for (int b = 0; b < 6; b++) L[b] = 0.f;
    } else {
        float meann = (s / Nf - dmin) / drng;
        float t = 1.f - meann;
        float w1 = t * t;
#pragma unroll
        for (int b = 0; b < 6; b++) L[b] = (hl[b] - dmin) / drng * w1;
    }
    int gb = 0;
    if (rng != 0.f) {
        float chpb = __fmul_rn(__fdiv_rn(__fsub_rn(0.f, mn), rng), 256.f);
        int g = (int)truncf(__fsub_rn(__fmul_rn(chpb, 6.f), 1.f));
        gb = min(5, max(0, g));
    }
    float mmin = FLT_MAX, mmax = -FLT_MAX, s2 = 0.f;
#pragma unroll
    for (int b = 0; b < 6; b++) {
        unsigned cnt = h2[b];
        if (c > 0 && b == gb) cnt -= (unsigned)Nb;
        if (cnt) {
            mmin = fminf(mmin, L[b]); mmax = fmaxf(mmax, L[b]);
            s2 += (float)cnt * L[b];
        }
    }
    if (c > 0) { mmin = fminf(mmin, 0.f); mmax = fmaxf(mmax, 0.f); }
    float mrng = mmax - mmin;
    if (mrng == 0.f) {
#pragma unroll
        for (int b = 0; b < 6; b++) g_M[gc][b] = 0.f;
        g_Z[gc] = 0.f;
    } else {
        float mmean = s2 / Nf;
        float t = mmax - mmean;
        float w2 = t * t;
#pragma unroll
        for (int b = 0; b < 6; b++) g_M[gc][b] = (L[b] - mmin) / mrng * w2;
        g_Z[gc] = (0.f - mmin) / mrng * w2;
    }
}

// -------- K4: proc[p] = sum_c M[c][gidx]; fused pminmax when CS==C ---------
template <int C, int H, int W, int CS>
__device__ __forceinline__ void proc_layer(size_t gidxoff, int procoff,
                                           int choff, int pxblk, int cslice,
                                           int layer) {
    constexpr int HW = H * W;
    constexpr int NQ = HW / 4;
    __shared__ float sM[CS * 6];
    __shared__ float sZ[CS];
    const int cbeg = cslice * CS;
    for (int i = threadIdx.x; i < CS * 6; i += 256)
        sM[i] = ((const float*)g_M)[(choff + cbeg) * 6 + i];
    for (int i = threadIdx.x; i < CS; i += 256) sZ[i] = g_Z[choff + cbeg + i];
    __syncthreads();

    int q = pxblk * 256 + threadIdx.x;
    bool act = q < NQ;
    bool bf0 = false, bf1 = false, bf2 = false, bf3 = false;
    if (act) {
        if constexpr (W % 4 == 0) {
            constexpr int W4 = W / 4;
            int row = q / W4, col = q - row * W4;
            bool br = (row == 0) | (row == H - 1);
            bf0 = br | (col == 0); bf1 = br; bf2 = br;
            bf3 = br | (col == W4 - 1);
        } else {
            int e = q * 4;
#pragma unroll
            for (int k = 0; k < 4; k++) {
                int y = (e + k) / W, x = (e + k) - y * W;
                bool bb = (y == 0) | (x == 0) | (y == H - 1) | (x == W - 1);
                if (k == 0) bf0 = bb; else if (k == 1) bf1 = bb;
                else if (k == 2) bf2 = bb; else bf3 = bb;
            }
        }
    }
    bool anyb = __any_sync(0xffffffffu, act && (bf0 | bf1 | bf2 | bf3));
    float a0 = 0.f, a1 = 0.f, a2 = 0.f, a3 = 0.f;
    if (act) {
        const uchar4* gp = (const uchar4*)(g_gidx + gidxoff) + q;
        if (!anyb) {
#pragma unroll 8
            for (int cc = 0; cc < CS; cc++) {
                uchar4 gv = gp[(size_t)(cbeg + cc) * NQ];
                const float* mc = sM + cc * 6;
                a0 += mc[gv.x]; a1 += mc[gv.y]; a2 += mc[gv.z]; a3 += mc[gv.w];
            }
        } else {
#pragma unroll 8
            for (int cc = 0; cc < CS; cc++) {
                uchar4 gv = gp[(size_t)(cbeg + cc) * NQ];
                const float* mc = sM + cc * 6;
                bool ch0 = (cbeg + cc) == 0;   // layer ch 0 keeps border
                float z = sZ[cc];
                a0 += (bf0 && !ch0) ? z : mc[gv.x];
                a1 += (bf1 && !ch0) ? z : mc[gv.y];
                a2 += (bf2 && !ch0) ? z : mc[gv.z];
                a3 += (bf3 && !ch0) ? z : mc[gv.w];
            }
        }
        if constexpr (CS == C) {
            ((float4*)(g_proc + procoff))[q] = make_float4(a0, a1, a2, a3);
        } else {
            float* pp = g_proc + procoff + q * 4;
            atomicAdd(pp + 0, a0); atomicAdd(pp + 1, a1);
            atomicAdd(pp + 2, a2); atomicAdd(pp + 3, a3);
        }
    }
    if constexpr (CS == C) {
        float vmn = act ? fminf(fminf(a0, a1), fminf(a2, a3)) : FLT_MAX;
        float vmx = act ? fmaxf(fmaxf(a0, a1), fmaxf(a2, a3)) : -FLT_MAX;
        __shared__ unsigned smn[8], smx[8];
        unsigned emn = __reduce_min_sync(0xffffffffu, fenc(vmn));
        unsigned emx = __reduce_max_sync(0xffffffffu, fenc(vmx));
        if ((threadIdx.x & 31) == 0) {
            smn[threadIdx.x >> 5] = emn; smx[threadIdx.x >> 5] = emx;
        }
        __syncthreads();
        if (threadIdx.x == 0) {
            unsigned a = smn[0], b = smx[0];
#pragma unroll
            for (int w = 1; w < 8; w++) { a = min(a, smn[w]); b = max(b, smx[w]); }
            atomicMin(&g_pmin[layer], a);
            atomicMax(&g_pmax[layer], b);
        }
    }
}

__global__ __launch_bounds__(256) void k_proc_all() {
    int b = blockIdx.x;
    if (b < 225)       proc_layer<64, 480, 480, 64>(0, 0, 0, b, 0, 0);
    else if (b < 282)  proc_layer<128, 240, 240, 128>(14745600u, 230400, 64, b - 225, 0, 1);
    else if (b < 297)  proc_layer<256, 120, 120, 256>(22118400u, 288000, 192, b - 282, 0, 2);
    else if (b < 329) { int i = b - 297;
                        proc_layer<512, 60, 60, 64>(25804800u, 302400, 448, i & 3, i >> 2, 3); }
    else               proc_layer<512, 30, 30, 64>(27648000u, 306000, 960, 0, b - 329, 4);
}

// -------- K5: pmin/pmax for l4,l5 (atomic-accumulated proc) ----------------
__global__ void k_mm45() {
    int b = blockIdx.x;
    int off = (b < 4) ? 302400 + b * 900 : 306000;
    int layer = (b < 4) ? 3 : 4;
    float mn = FLT_MAX, mx = -FLT_MAX;
    for (int i = threadIdx.x; i < 900; i += 256) {
        float v = g_proc[off + i];
        mn = fminf(mn, v); mx = fmaxf(mx, v);
    }
    __shared__ unsigned smn[8], smx[8];
    unsigned emn = __reduce_min_sync(0xffffffffu, fenc(mn));
    unsigned emx = __reduce_max_sync(0xffffffffu, fenc(mx));
    if ((threadIdx.x & 31) == 0) {
        smn[threadIdx.x >> 5] = emn; smx[threadIdx.x >> 5] = emx;
    }
    __syncthreads();
    if (threadIdx.x == 0) {
        unsigned a = smn[0], bb = smx[0];
#pragma unroll
        for (int w = 1; w < 8; w++) { a = min(a, smn[w]); bb = max(bb, smx[w]); }
        atomicMin(&g_pmin[layer], a);
        atomicMax(&g_pmax[layer], bb);
    }
}

// -------- K6: resize (jax bilinear, antialias) + fused normalize/threshold -
template <int S>
__device__ __forceinline__ void resize_layer(int b, int procoff, int layer) {
    int idx = b * 256 + threadIdx.x;   // 57600 = 225*256 exact
    int oy = idx / 240, ox = idx - oy * 240;
    float pmn = fdec(g_pmin[layer]);
    float pmx = fdec(g_pmax[layer]);
    float prng = pmx - pmn;
    constexpr float inv = (float)S / 240.f;
    constexpr float ks = (S > 240) ? inv : 1.f;
    constexpr float iks = 1.f / ks;
    float fy = (oy + 0.5f) * inv - 0.5f;
    float fx = (ox + 0.5f) * inv - 0.5f;
    int y0 = max(0, (int)ceilf(fy - ks)), y1 = min(S - 1, (int)floorf(fy + ks));
    int x0 = max(0, (int)ceilf(fx - ks)), x1 = min(S - 1, (int)floorf(fx + ks));
    float wy[4], wx[4];
    float sy = 0.f, sx = 0.f;
#pragma unroll
    for (int j = 0; j < 4; j++) {
        int yy = y0 + j;
        float w = (yy <= y1) ? fmaxf(0.f, 1.f - fabsf(fy - (float)yy) * iks) : 0.f;
        wy[j] = w; sy += w;
        int xx = x0 + j;
        float v = (xx <= x1) ? fmaxf(0.f, 1.f - fabsf(fx - (float)xx) * iks) : 0.f;
        wx[j] = v; sx += v;
    }
#pragma unroll
    for (int j = 0; j < 4; j++) {
        wy[j] = __fdiv_rn(wy[j], sy);
        wx[j] = __fdiv_rn(wx[j], sx);
    }
    const float* p = g_proc + procoff;
    float acc = 0.f;
#pragma unroll
    for (int jy = 0; jy < 4; jy++) {
        if (y0 + jy > y1) break;
        const float* row = p + (y0 + jy) * S;
        float r = 0.f;
#pragma unroll
        for (int jx = 0; jx < 4; jx++) {
            if (x0 + jx > x1) break;
            float v = row[x0 + jx];
            float n = (prng == 0.f) ? 0.f : __fdiv_rn(__fsub_rn(v, pmn), prng);
            n = (n < 0.2f) ? 0.f : n;
            r += wx[jx] * n;
        }
        acc += wy[jy] * r;
    }
    g_resized[layer * 57600 + idx] = acc;

    __shared__ unsigned smn[8], smx[8];
    __shared__ float ssum[8];
    unsigned emn = __reduce_min_sync(0xffffffffu, fenc(acc));
    unsigned emx = __reduce_max_sync(0xffffffffu, fenc(acc));
    float wsum = acc;
#pragma unroll
    for (int o = 16; o; o >>= 1) wsum += __shfl_xor_sync(0xffffffffu, wsum, o);
    if ((threadIdx.x & 31) == 0) {
        int w = threadIdx.x >> 5;
        smn[w] = emn; smx[w] = emx; ssum[w] = wsum;
    }
    __syncthreads();
    if (threadIdx.x == 0) {
        unsigned a = smn[0], bb = smx[0]; float s = ssum[0];
#pragma unroll
        for (int w = 1; w < 8; w++) {
            a = min(a, smn[w]); bb = max(bb, smx[w]); s += ssum[w];
        }
        atomicMin(&g_rmin[layer], a);
        atomicMax(&g_rmax[layer], bb);
        atomicAdd(&g_rsum[layer], s);
    }
}

__global__ __launch_bounds__(256) void k_resize_all() {
    int b = blockIdx.x;
    if (b < 225)      resize_layer<480>(b, 0, 0);
    else if (b < 450) resize_layer<240>(b - 225, 230400, 1);
    else if (b < 675) resize_layer<120>(b - 450, 288000, 2);
    else if (b < 900) resize_layer<60>(b - 675, 302400, 3);
    else              resize_layer<30>(b - 900, 306000, 4);
}

// -------- K7: final groups + sum -------------------------------------------
__global__ void k_final(float* __restrict__ out) {
    int idx = blockIdx.x * 256 + threadIdx.x;   // 57600
    float s = 0.f;
#pragma unroll
    for (int l = 0; l < 5; l++) {
        float v = g_resized[l * 57600 + idx];
        float rmn = fdec(g_rmin[l]);
        float rmx = fdec(g_rmax[l]);
        float rrng = rmx - rmn;
        float rmean = g_rsum[l] / 57600.f;
        float t = rmx - rmean;
        float w3 = t * t;
        float g = (rrng == 0.f || w3 == 0.f)
                  ? 0.f
                  : __fmul_rn(__fdiv_rn(__fsub_rn(v, rmn), rrng), 256.f);
        s += g;
        out[57600 + idx * 5 + l] = g;
    }
    out[idx] = s;
}

extern "C" void kernel_launch(void* const* d_in, const int* in_sizes, int n_in,
                              void* d_out, int out_size) {
    const float* l1 = (const float*)d_in[0];
    const float* l2 = (const float*)d_in[1];
    const float* l3 = (const float*)d_in[2];
    const float* l4 = (const float*)d_in[3];
    const float* l5 = (const float*)d_in[4];
    float* out = (float*)d_out;

    k_init<<<35, 256>>>();
    // per-layer interleave: hist_i re-reads layer i while it is L2-resident
    k_mm1<<<960, 256>>>(l1);  k_h1<<<960, 256>>>(l1);
    k_mm2<<<512, 256>>>(l2);  k_h2<<<512, 256>>>(l2);
    k_mm3<<<256, 256>>>(l3);  k_h3<<<256, 256>>>(l3);
    k_mm4<<<512, 256>>>(l4);  k_h4<<<512, 256>>>(l4);
    k_mm5<<<512, 256>>>(l5);  k_h5<<<512, 256>>>(l5);
    k_stats_all<<<46, 32>>>();
    k_proc_all<<<337, 256>>>();
    k_mm45<<<5, 256>>>();
    k_resize_all<<<1125, 256>>>();
    k_final<<<225, 256>>>(out);
}

// round 5
// speedup vs baseline: 1.1493x; 1.1493x over previous
#include <cuda_runtime.h>
#include <cuda_bf16.h>
#include <math.h>
#include <float.h>
#include <stdint.h>

// ---------------------------------------------------------------------------
// DeepRare, fully fused: ONE persistent kernel (740 blocks, single wave,
// software grid barriers) + tiny init kernel. Phases:
//   P1 minmax -> P2 hist+gidx (L2-hot re-read) -> P3 stats -> P4 proc
//   -> P5 mm45 -> P6 resize -> P7 final.
// ---------------------------------------------------------------------------

#define NCH 1472
#define GIDX_TOTAL 28108800
#define NB 740          // 148 SMs x 5 blocks: guaranteed co-resident

__device__ unsigned g_bar;
__device__ unsigned g_cmin[NCH], g_cmax[NCH];
__device__ unsigned g_hist[NCH][6], g_hist2[NCH][6];
__device__ float g_M[NCH][6], g_Z[NCH];
__device__ __align__(16) unsigned char g_gidx[GIDX_TOTAL];
__device__ __align__(16) float g_proc[306912];
__device__ unsigned g_pmin[5], g_pmax[5];
__device__ float g_resized[5 * 57600];
__device__ unsigned g_rmin[5], g_rmax[5];
__device__ float g_rsum[5];

// order-preserving float<->uint encoding for atomic min/max
__device__ __forceinline__ unsigned fenc(float f) {
    unsigned u = __float_as_uint(f);
    return (u & 0x80000000u) ? ~u : (u | 0x80000000u);
}
__device__ __forceinline__ float fdec(unsigned e) {
    return (e & 0x80000000u) ? __uint_as_float(e & 0x7fffffffu)
                             : __uint_as_float(~e);
}

// grid-wide barrier: all NB blocks resident (single wave) by construction
__device__ __forceinline__ void gridbar(unsigned tgt) {
    __syncthreads();
    if (threadIdx.x == 0) {
        __threadfence();
        atomicAdd(&g_bar, 1u);
        volatile unsigned* p = &g_bar;
        while (*p < tgt) { __nanosleep(20); }
        __threadfence();
    }
    __syncthreads();
}

__global__ void k_init() {
    int i = blockIdx.x * 256 + threadIdx.x;
    if (i == 0) g_bar = 0u;
    if (i < NCH * 6) {
        ((unsigned*)g_hist)[i] = 0u;
        ((unsigned*)g_hist2)[i] = 0u;
    }
    if (i < NCH) { g_cmin[i] = 0xffffffffu; g_cmax[i] = 0u; }
    if (i < 4500) g_proc[302400 + i] = 0.f;   // l4+l5 (atomic-accumulated)
    if (i < 5) {
        g_pmin[i] = 0xffffffffu; g_pmax[i] = 0u;
        g_rmin[i] = 0xffffffffu; g_rmax[i] = 0u;
        g_rsum[i] = 0.f;
    }
}

// ---- masked float4 load (borders -> 0), constexpr unrolled ----------------
template <int H, int W>
__device__ __forceinline__ void mask4(int fc, float4 v,
                                      float& v0, float& v1, float& v2, float& v3) {
    if constexpr (W % 4 == 0) {
        constexpr int W4 = W / 4;
        int row = fc / W4;
        int col = fc - row * W4;
        bool br = (row == 0) | (row == H - 1);
        v0 = (br | (col == 0))      ? 0.f : v.x;
        v1 = br                      ? 0.f : v.y;
        v2 = br                      ? 0.f : v.z;
        v3 = (br | (col == W4 - 1)) ? 0.f : v.w;
    } else {
        int e = fc * 4;
        int y0 = e / W, x0 = e - y0 * W;
        int y1 = (e+1) / W, x1 = (e+1) - y1 * W;
        int y2 = (e+2) / W, x2 = (e+2) - y2 * W;
        int y3 = (e+3) / W, x3 = (e+3) - y3 * W;
        v0 = ((y0==0)|(x0==0)|(y0==H-1)|(x0==W-1)) ? 0.f : v.x;
        v1 = ((y1==0)|(x1==0)|(y1==H-1)|(x1==W-1)) ? 0.f : v.y;
        v2 = ((y2==0)|(x2==0)|(y2==H-1)|(x2==W-1)) ? 0.f : v.z;
        v3 = ((y3==0)|(x3==0)|(y3==H-1)|(x3==W-1)) ? 0.f : v.w;
    }
}

// -------- P1: per-channel min/max over zero-bordered channel ---------------
template <int H, int W, int SLICES>
__device__ __forceinline__ void mm_layer(const float* __restrict__ in,
                                         int choff, int blk) {
    constexpr int HWf4 = H * W / 4;
    constexpr int SL = HWf4 / SLICES;
    constexpr int F4PT = (SL + 255) / 256;
    const int c = blk / SLICES;
    const int s = blk - c * SLICES;
    const float4* p4 = (const float4*)in + (size_t)c * HWf4 + s * SL;
    const int fbase = s * SL;
    float mn = FLT_MAX, mx = -FLT_MAX;
#pragma unroll
    for (int j = 0; j < F4PT; j++) {
        int fl = j * 256 + threadIdx.x;
        if (SL % 256 == 0 || fl < SL) {
            float4 v = p4[fl];
            float v0, v1, v2, v3;
            mask4<H, W>(fbase + fl, v, v0, v1, v2, v3);
            mn = fminf(mn, fminf(fminf(v0, v1), fminf(v2, v3)));
            mx = fmaxf(mx, fmaxf(fmaxf(v0, v1), fmaxf(v2, v3)));
        }
    }
    unsigned emn = __reduce_min_sync(0xffffffffu, fenc(mn));
    unsigned emx = __reduce_max_sync(0xffffffffu, fenc(mx));
    if ((threadIdx.x & 31) == 0) {
        atomicMin(&g_cmin[choff + c], emn);
        atomicMax(&g_cmax[choff + c], emx);
    }
}

// -------- P2: dual 6-bin histogram + gidx map ------------------------------
template <int H, int W, int SLICES>
__device__ __forceinline__ void hist_layer(const float* __restrict__ in,
                                           int choff, size_t gidxoff, int blk,
                                           unsigned* sh) {
    constexpr int HWf4 = H * W / 4;
    constexpr int SL = HWf4 / SLICES;
    constexpr int F4PT = (SL + 255) / 256;
    const int c = blk / SLICES;
    const int s = blk - c * SLICES;
    const int gc = choff + c;
    const float4* p4 = (const float4*)in + (size_t)c * HWf4 + s * SL;
    uchar4* go = (uchar4*)(g_gidx + gidxoff) + (size_t)c * HWf4 + s * SL;
    const int fbase = s * SL;
    const float mn = fdec(g_cmin[gc]);
    const float mx = fdec(g_cmax[gc]);
    const float rng = mx - mn;
    const bool zr = (rng == 0.f);
    const float ib = 1.0f / (256.0f / 6.0f);
    unsigned long long pk1 = 0, pk2 = 0;   // 6 x 10-bit packed counters
#pragma unroll
    for (int j = 0; j < F4PT; j++) {
        int fl = j * 256 + threadIdx.x;
        if (SL % 256 == 0 || fl < SL) {
            float4 v = p4[fl];
            float vv[4];
            mask4<H, W>(fbase + fl, v, vv[0], vv[1], vv[2], vv[3]);
            unsigned gb[4];
#pragma unroll
            for (int k = 0; k < 4; k++) {
                float q = zr ? 0.f : __fdiv_rn(__fsub_rn(vv[k], mn), rng);
                float chp = __fmul_rn(q, 256.f);
                int bin = (int)floorf(__fmul_rn(chp, ib));
                bin = min(5, max(0, bin));
                int g = (int)truncf(__fsub_rn(__fmul_rn(chp, 6.f), 1.f));
                g = min(5, max(0, g));
                pk1 += 1ull << (bin * 10);
                pk2 += 1ull << (g * 10);
                gb[k] = (unsigned)g;
            }
            go[fl] = make_uchar4(gb[0], gb[1], gb[2], gb[3]);
        }
    }
    if (threadIdx.x < 12) sh[threadIdx.x] = 0;
    __syncthreads();
#pragma unroll
    for (int b6 = 0; b6 < 6; b6++) {
        unsigned c1 = (unsigned)(pk1 >> (b6 * 10)) & 1023u;
        unsigned c2 = (unsigned)(pk2 >> (b6 * 10)) & 1023u;
        c1 = __reduce_add_sync(0xffffffffu, c1);
        c2 = __reduce_add_sync(0xffffffffu, c2);
        if ((threadIdx.x & 31) == 0) {
            if (c1) atomicAdd(&sh[b6], c1);
            if (c2) atomicAdd(&sh[6 + b6], c2);
        }
    }
    __syncthreads();
    if (threadIdx.x < 6 && sh[threadIdx.x])
        atomicAdd(&g_hist[gc][threadIdx.x], sh[threadIdx.x]);
    if (threadIdx.x >= 6 && threadIdx.x < 12 && sh[threadIdx.x])
        atomicAdd(&g_hist2[gc][threadIdx.x - 6], sh[threadIdx.x]);
    __syncthreads();
}

// -------- P3: closed-form per-channel tables -------------------------------
__device__ __forceinline__ void stats_ch(int gc) {
    int choff, H, W;
    if (gc < 64)       { choff = 0;   H = 480; W = 480; }
    else if (gc < 192) { choff = 64;  H = 240; W = 240; }
    else if (gc < 448) { choff = 192; H = 120; W = 120; }
    else if (gc < 960) { choff = 448; H = 60;  W = 60;  }
    else               { choff = 960; H = 30;  W = 30;  }
    const int c = gc - choff;
    const float Nf = (float)(H * W);
    const int Nb = 2 * (H + W) - 4;

    float mn = fdec(g_cmin[gc]), mx = fdec(g_cmax[gc]);
    float rng = mx - mn;

    float hl[6]; unsigned h2[6];
#pragma unroll
    for (int b = 0; b < 6; b++) {
        float pr = __fadd_rn(__fdiv_rn((float)g_hist[gc][b], Nf), 1e-4f);
        hl[b] = -logf(pr);
        h2[b] = g_hist2[gc][b];
    }
    float dmin = FLT_MAX, dmax = -FLT_MAX, s = 0.f;
#pragma unroll
    for (int b = 0; b < 6; b++) if (h2[b]) {
        dmin = fminf(dmin, hl[b]); dmax = fmaxf(dmax, hl[b]);
        s += (float)h2[b] * hl[b];
    }
    float drng = dmax - dmin;
    float L[6];
    if (drng == 0.f) {
#pragma unroll
        for (int b = 0; b < 6; b++) L[b] = 0.f;
    } else {
        float meann = (s / Nf - dmin) / drng;
        float t = 1.f - meann;
        float w1 = t * t;
#pragma unroll
        for (int b = 0; b < 6; b++) L[b] = (hl[b] - dmin) / drng * w1;
    }
    int gb = 0;
    if (rng != 0.f) {
        float chpb = __fmul_rn(__fdiv_rn(__fsub_rn(0.f, mn), rng), 256.f);
        int g = (int)truncf(__fsub_rn(__fmul_rn(chpb, 6.f), 1.f));
        gb = min(5, max(0, g));
    }
    float mmin = FLT_MAX, mmax = -FLT_MAX, s2 = 0.f;
#pragma unroll
    for (int b = 0; b < 6; b++) {
        unsigned cnt = h2[b];
        if (c > 0 && b == gb) cnt -= (unsigned)Nb;
        if (cnt) {
            mmin = fminf(mmin, L[b]); mmax = fmaxf(mmax, L[b]);
            s2 += (float)cnt * L[b];
        }
    }
    if (c > 0) { mmin = fminf(mmin, 0.f); mmax = fmaxf(mmax, 0.f); }
    float mrng = mmax - mmin;
    if (mrng == 0.f) {
#pragma unroll
        for (int b = 0; b < 6; b++) g_M[gc][b] = 0.f;
        g_Z[gc] = 0.f;
    } else {
        float mmean = s2 / Nf;
        float t = mmax - mmean;
        float w2 = t * t;
#pragma unroll
        for (int b = 0; b < 6; b++) g_M[gc][b] = (L[b] - mmin) / mrng * w2;
        g_Z[gc] = (0.f - mmin) / mrng * w2;
    }
}

// -------- P4: proc[p] = sum_c M[c][gidx]; fused pminmax when CS==C ---------
template <int C, int H, int W, int CS>
__device__ __forceinline__ void proc_layer(size_t gidxoff, int procoff,
                                           int choff, int pxblk, int cslice,
                                           int layer, float* sM, float* sZ,
                                           unsigned* sred) {
    constexpr int HW = H * W;
    constexpr int NQ = HW / 4;
    const int cbeg = cslice * CS;
    for (int i = threadIdx.x; i < CS * 6; i += 256)
        sM[i] = ((const float*)g_M)[(choff + cbeg) * 6 + i];
    for (int i = threadIdx.x; i < CS; i += 256) sZ[i] = g_Z[choff + cbeg + i];
    __syncthreads();

    int q = pxblk * 256 + threadIdx.x;
    bool act = q < NQ;
    bool bf0 = false, bf1 = false, bf2 = false, bf3 = false;
    if (act) {
        if constexpr (W % 4 == 0) {
            constexpr int W4 = W / 4;
            int row = q / W4, col = q - row * W4;
            bool br = (row == 0) | (row == H - 1);
            bf0 = br | (col == 0); bf1 = br; bf2 = br;
            bf3 = br | (col == W4 - 1);
        } else {
            int e = q * 4;
#pragma unroll
            for (int k = 0; k < 4; k++) {
                int y = (e + k) / W, x = (e + k) - y * W;
                bool bb = (y == 0) | (x == 0) | (y == H - 1) | (x == W - 1);
                if (k == 0) bf0 = bb; else if (k == 1) bf1 = bb;
                else if (k == 2) bf2 = bb; else bf3 = bb;
            }
        }
    }
    bool anyb = __any_sync(0xffffffffu, act && (bf0 | bf1 | bf2 | bf3));
    float a0 = 0.f, a1 = 0.f, a2 = 0.f, a3 = 0.f;
    if (act) {
        const uchar4* gp = (const uchar4*)(g_gidx + gidxoff) + q;
        if (!anyb) {
#pragma unroll 8
            for (int cc = 0; cc < CS; cc++) {
                uchar4 gv = gp[(size_t)(cbeg + cc) * NQ];
                const float* mc = sM + cc * 6;
                a0 += mc[gv.x]; a1 += mc[gv.y]; a2 += mc[gv.z]; a3 += mc[gv.w];
            }
        } else {
#pragma unroll 8
            for (int cc = 0; cc < CS; cc++) {
                uchar4 gv = gp[(size_t)(cbeg + cc) * NQ];
                const float* mc = sM + cc * 6;
                bool ch0 = (cbeg + cc) == 0;   // layer ch 0 keeps border
                float z = sZ[cc];
                a0 += (bf0 && !ch0) ? z : mc[gv.x];
                a1 += (bf1 && !ch0) ? z : mc[gv.y];
                a2 += (bf2 && !ch0) ? z : mc[gv.z];
                a3 += (bf3 && !ch0) ? z : mc[gv.w];
            }
        }
        if constexpr (CS == C) {
            ((float4*)(g_proc + procoff))[q] = make_float4(a0, a1, a2, a3);
        } else {
            float* pp = g_proc + procoff + q * 4;
            atomicAdd(pp + 0, a0); atomicAdd(pp + 1, a1);
            atomicAdd(pp + 2, a2); atomicAdd(pp + 3, a3);
        }
    }
    if constexpr (CS == C) {
        float vmn = act ? fminf(fminf(a0, a1), fminf(a2, a3)) : FLT_MAX;
        float vmx = act ? fmaxf(fmaxf(a0, a1), fmaxf(a2, a3)) : -FLT_MAX;
        unsigned* smn = sred; unsigned* smx = sred + 8;
        unsigned emn = __reduce_min_sync(0xffffffffu, fenc(vmn));
        unsigned emx = __reduce_max_sync(0xffffffffu, fenc(vmx));
        if ((threadIdx.x & 31) == 0) {
            smn[threadIdx.x >> 5] = emn; smx[threadIdx.x >> 5] = emx;
        }
        __syncthreads();
        if (threadIdx.x == 0) {
            unsigned a = smn[0], b = smx[0];
#pragma unroll
            for (int w = 1; w < 8; w++) { a = min(a, smn[w]); b = max(b, smx[w]); }
            atomicMin(&g_pmin[layer], a);
            atomicMax(&g_pmax[layer], b);
        }
        __syncthreads();
    }
}

// -------- P6: resize + fused normalize/threshold + r-stats -----------------
template <int S>
__device__ __forceinline__ void resize_layer(int b, int procoff, int layer,
                                             unsigned* sred, float* ssum) {
    int idx = b * 256 + threadIdx.x;   // 57600 = 225*256 exact
    int oy = idx / 240, ox = idx - oy * 240;
    float pmn = fdec(g_pmin[layer]);
    float pmx = fdec(g_pmax[layer]);
    float prng = pmx - pmn;
    constexpr float inv = (float)S / 240.f;
    constexpr float ks = (S > 240) ? inv : 1.f;
    constexpr float iks = 1.f / ks;
    float fy = (oy + 0.5f) * inv - 0.5f;
    float fx = (ox + 0.5f) * inv - 0.5f;
    int y0 = max(0, (int)ceilf(fy - ks)), y1 = min(S - 1, (int)floorf(fy + ks));
    int x0 = max(0, (int)ceilf(fx - ks)), x1 = min(S - 1, (int)floorf(fx + ks));
    float wy[4], wx[4];
    float sy = 0.f, sx = 0.f;
#pragma unroll
    for (int j = 0; j < 4; j++) {
        int yy = y0 + j;
        float w = (yy <= y1) ? fmaxf(0.f, 1.f - fabsf(fy - (float)yy) * iks) : 0.f;
        wy[j] = w; sy += w;
        int xx = x0 + j;
        float v = (xx <= x1) ? fmaxf(0.f, 1.f - fabsf(fx - (float)xx) * iks) : 0.f;
        wx[j] = v; sx += v;
    }
#pragma unroll
    for (int j = 0; j < 4; j++) {
        wy[j] = __fdiv_rn(wy[j], sy);
        wx[j] = __fdiv_rn(wx[j], sx);
    }
    const float* p = g_proc + procoff;
    float acc = 0.f;
#pragma unroll
    for (int jy = 0; jy < 4; jy++) {
        if (y0 + jy > y1) break;
        const float* row = p + (y0 + jy) * S;
        float r = 0.f;
#pragma unroll
        for (int jx = 0; jx < 4; jx++) {
            if (x0 + jx > x1) break;
            float v = row[x0 + jx];
            float n = (prng == 0.f) ? 0.f : __fdiv_rn(__fsub_rn(v, pmn), prng);
            n = (n < 0.2f) ? 0.f : n;
            r += wx[jx] * n;
        }
        acc += wy[jy] * r;
    }
    g_resized[layer * 57600 + idx] = acc;

    unsigned* smn = sred; unsigned* smx = sred + 8;
    unsigned emn = __reduce_min_sync(0xffffffffu, fenc(acc));
    unsigned emx = __reduce_max_sync(0xffffffffu, fenc(acc));
    float wsum = acc;
#pragma unroll
    for (int o = 16; o; o >>= 1) wsum += __shfl_xor_sync(0xffffffffu, wsum, o);
    if ((threadIdx.x & 31) == 0) {
        int w = threadIdx.x >> 5;
        smn[w] = emn; smx[w] = emx; ssum[w] = wsum;
    }
    __syncthreads();
    if (threadIdx.x == 0) {
        unsigned a = smn[0], bb = smx[0]; float s = ssum[0];
#pragma unroll
        for (int w = 1; w < 8; w++) {
            a = min(a, smn[w]); bb = max(bb, smx[w]); s += ssum[w];
        }
        atomicMin(&g_rmin[layer], a);
        atomicMax(&g_rmax[layer], bb);
        atomicAdd(&g_rsum[layer], s);
    }
    __syncthreads();
}

// ---------------------------- the fused kernel -----------------------------
__global__ __launch_bounds__(256, 5) void k_main(
    const float* __restrict__ l1, const float* __restrict__ l2,
    const float* __restrict__ l3, const float* __restrict__ l4,
    const float* __restrict__ l5, float* __restrict__ out) {
    __shared__ float sM[256 * 6];
    __shared__ float sZ[256];
    __shared__ unsigned sred[16];
    __shared__ float ssum[8];
    const int blk = blockIdx.x;

    // ---- P1: minmax (each block: up to 4 chunks of the 2752) ----
    for (int k = 0; k < 4; k++) {
        int b = blk + k * NB;
        if (b >= 2752) break;
        if (b < 960)       mm_layer<480, 480, 15>(l1, 0, b);
        else if (b < 1472) mm_layer<240, 240, 4>(l2, 64, b - 960);
        else if (b < 1728) mm_layer<120, 120, 1>(l3, 192, b - 1472);
        else if (b < 2240) mm_layer<60, 60, 1>(l4, 448, b - 1728);
        else               mm_layer<30, 30, 1>(l5, 960, b - 2240);
    }
    gridbar(1 * NB);

    // ---- P2: hist + gidx (same chunks; input is L2-resident) ----
    for (int k = 0; k < 4; k++) {
        int b = blk + k * NB;
        if (b >= 2752) break;
        if (b < 960)       hist_layer<480, 480, 15>(l1, 0, 0, b, sred);
        else if (b < 1472) hist_layer<240, 240, 4>(l2, 64, 14745600u, b - 960, sred);
        else if (b < 1728) hist_layer<120, 120, 1>(l3, 192, 22118400u, b - 1472, sred);
        else if (b < 2240) hist_layer<60, 60, 1>(l4, 448, 25804800u, b - 1728, sred);
        else               hist_layer<30, 30, 1>(l5, 960, 27648000u, b - 2240, sred);
    }
    gridbar(2 * NB);

    // ---- P3: per-channel tables ----
    {
        int gc = blk * 256 + threadIdx.x;
        if (gc < NCH) stats_ch(gc);
    }
    gridbar(3 * NB);

    // ---- P4: proc sums (337 work blocks) ----
    {
        int wb = blk;
        if (wb < 225)       proc_layer<64, 480, 480, 64>(0, 0, 0, wb, 0, 0, sM, sZ, sred);
        else if (wb < 282)  proc_layer<128, 240, 240, 128>(14745600u, 230400, 64, wb - 225, 0, 1, sM, sZ, sred);
        else if (wb < 297)  proc_layer<256, 120, 120, 256>(22118400u, 288000, 192, wb - 282, 0, 2, sM, sZ, sred);
        else if (wb < 329) { int i = wb - 297;
                             proc_layer<512, 60, 60, 64>(25804800u, 302400, 448, i & 3, i >> 2, 3, sM, sZ, sred); }
        else if (wb < 337)  proc_layer<512, 30, 30, 64>(27648000u, 306000, 960, 0, wb - 329, 4, sM, sZ, sred);
    }
    gridbar(4 * NB);

    // ---- P5: pmin/pmax for l4,l5 ----
    if (blk < 5) {
        int off = (blk < 4) ? 302400 + blk * 900 : 306000;
        int layer = (blk < 4) ? 3 : 4;
        float mn = FLT_MAX, mx = -FLT_MAX;
        for (int i = threadIdx.x; i < 900; i += 256) {
            float v = g_proc[off + i];
            mn = fminf(mn, v); mx = fmaxf(mx, v);
        }
        unsigned* smn = sred; unsigned* smx = sred + 8;
        unsigned emn = __reduce_min_sync(0xffffffffu, fenc(mn));
        unsigned emx = __reduce_max_sync(0xffffffffu, fenc(mx));
        if ((threadIdx.x & 31) == 0) {
            smn[threadIdx.x >> 5] = emn; smx[threadIdx.x >> 5] = emx;
        }
        __syncthreads();
        if (threadIdx.x == 0) {
            unsigned a = smn[0], bb = smx[0];
#pragma unroll
            for (int w = 1; w < 8; w++) { a = min(a, smn[w]); bb = max(bb, smx[w]); }
            atomicMin(&g_pmin[layer], a);
            atomicMax(&g_pmax[layer], bb);
        }
    }
    gridbar(5 * NB);

    // ---- P6: resize (1125 work blocks over NB) ----
    for (int k = 0; k < 2; k++) {
        int wb = blk + k * NB;
        if (wb >= 1125) break;
        if (wb < 225)      resize_layer<480>(wb, 0, 0, sred, ssum);
        else if (wb < 450) resize_layer<240>(wb - 225, 230400, 1, sred, ssum);
        else if (wb < 675) resize_layer<120>(wb - 450, 288000, 2, sred, ssum);
        else if (wb < 900) resize_layer<60>(wb - 675, 302400, 3, sred, ssum);
        else               resize_layer<30>(wb - 900, 306000, 4, sred, ssum);
    }
    gridbar(6 * NB);

    // ---- P7: final groups + sum (225 work blocks) ----
    if (blk < 225) {
        int idx = blk * 256 + threadIdx.x;
        float s = 0.f;
#pragma unroll
        for (int l = 0; l < 5; l++) {
            float v = g_resized[l * 57600 + idx];
            float rmn = fdec(g_rmin[l]);
            float rmx = fdec(g_rmax[l]);
            float rrng = rmx - rmn;
            float rmean = g_rsum[l] / 57600.f;
            float t = rmx - rmean;
            float w3 = t * t;
            float g = (rrng == 0.f || w3 == 0.f)
                      ? 0.f
                      : __fmul_rn(__fdiv_rn(__fsub_rn(v, rmn), rrng), 256.f);
            s += g;
            out[57600 + idx * 5 + l] = g;
        }
        out[idx] = s;
    }
}

extern "C" void kernel_launch(void* const* d_in, const int* in_sizes, int n_in,
                              void* d_out, int out_size) {
    const float* l1 = (const float*)d_in[0];
    const float* l2 = (const float*)d_in[1];
    const float* l3 = (const float*)d_in[2];
    const float* l4 = (const float*)d_in[3];
    const float* l5 = (const float*)d_in[4];
    float* out = (float*)d_out;

    k_init<<<35, 256>>>();
    k_main<<<NB, 256>>>(l1, l2, l3, l4, l5, out);
}